// round 1
// baseline (speedup 1.0000x reference)
#include <cuda_runtime.h>

#define PLANES 96
#define IMG    512
#define OUTW   497   // 512 - 16 + 1

// per-plane partial accumulators (spread addresses -> no atomic contention)
__device__ double g_mse_parts[PLANES];
__device__ double g_ssim_parts[PLANES];

// 16-tap Gaussian, sigma=1.5, normalized (computed in high precision offline).
// Compile-time literals so ptxas emits FFMA-imm (rt_SMSP=1 -> 2x FFMA throughput).
__device__ constexpr float Wt[16] = {
    9.91165e-07f, 2.22474e-05f, 3.20180e-04f, 2.95456e-03f,
    1.748126e-02f, 6.631809e-02f, 1.6131382e-01f, 2.5158883e-01f,
    2.5158883e-01f, 1.6131382e-01f, 6.631809e-02f, 1.748126e-02f,
    2.95456e-03f, 3.20180e-04f, 2.22474e-05f, 9.91165e-07f};

__global__ void zero_accum_kernel() {
    int i = threadIdx.x;
    if (i < PLANES) { g_mse_parts[i] = 0.0; g_ssim_parts[i] = 0.0; }
}

__global__ __launch_bounds__(256, 4)
void ssim_mse_kernel(const float* __restrict__ img_o,
                     const float* __restrict__ img_t) {
    constexpr int TW = 32, TH = 32;     // output tile
    constexpr int LW = 47;              // loaded region = tile + 15 halo
    constexpr int LS = 48;              // smem row stride (16B-aligned float4 rows)
    constexpr int HS = 33;              // horizontal-result stride (kills STS bank conflicts)
    constexpr float C1 = 6.5025f;       // (0.01*255)^2
    constexpr float C2 = 58.5225f;      // (0.03*255)^2

    __shared__ float sS[LW * LS];       // (x1+x2)*255
    __shared__ float sD[LW * LS];       // (x1-x2)*255
    __shared__ float h0[LW * HS];       // hconv(s)
    __shared__ float h1[LW * HS];       // hconv(d)
    __shared__ float h2[LW * HS];       // hconv(s^2)
    __shared__ float h3[LW * HS];       // hconv(d^2)
    __shared__ float red_m[8], red_s[8];

    const int tid   = threadIdx.x;
    const int x0    = blockIdx.x * TW;
    const int y0    = blockIdx.y * TH;
    const int plane = blockIdx.z;
    const float* po = img_o + (size_t)plane * (IMG * IMG);
    const float* pt = img_t + (size_t)plane * (IMG * IMG);

    float mse_acc = 0.f;

    // ---- Phase 1: load halo region, form s/d, fuse MSE over owned 32x32 ----
    for (int i = tid; i < LW * LW; i += 256) {
        int r = i / LW;
        int c = i - r * LW;
        int gy = y0 + r, gx = x0 + c;
        float s = 0.f, d = 0.f;
        if (gy < IMG && gx < IMG) {
            float a  = po[gy * IMG + gx];
            float b  = pt[gy * IMG + gx];
            float df = a - b;
            s = (a + b) * 255.f;
            d = df * 255.f;
            if (r < TH && c < TW) mse_acc = fmaf(df, df, mse_acc);  // unique ownership
        }
        sS[r * LS + c] = s;
        sD[r * LS + c] = d;
    }
    __syncthreads();

    // ---- Phase 2: horizontal 16-tap conv of s, d, s^2, d^2 (4 outputs/thread) ----
    for (int task = tid; task < LW * 8; task += 256) {
        int r  = task >> 3;
        int qb = task & 7;                      // float4 index; col base = qb*4
        const float4* rowS = reinterpret_cast<const float4*>(sS + r * LS);
        const float4* rowD = reinterpret_cast<const float4*>(sD + r * LS);
        float aS[4]  = {0.f, 0.f, 0.f, 0.f};
        float aD[4]  = {0.f, 0.f, 0.f, 0.f};
        float aS2[4] = {0.f, 0.f, 0.f, 0.f};
        float aD2[4] = {0.f, 0.f, 0.f, 0.f};
        #pragma unroll
        for (int jc = 0; jc < 5; ++jc) {        // stream 5 float4 chunks (window = 19)
            float4 v4 = rowS[qb + jc];
            float4 w4 = rowD[qb + jc];
            float es[4] = {v4.x, v4.y, v4.z, v4.w};
            float ed[4] = {w4.x, w4.y, w4.z, w4.w};
            #pragma unroll
            for (int e = 0; e < 4; ++e) {
                int j = jc * 4 + e;
                if (j < 19) {
                    float vs = es[e], vd = ed[e];
                    float vs2 = vs * vs, vd2 = vd * vd;
                    #pragma unroll
                    for (int o = 0; o < 4; ++o) {
                        int k = j - o;
                        if (k >= 0 && k < 16) {
                            aS[o]  = fmaf(vs,  Wt[k], aS[o]);
                            aD[o]  = fmaf(vd,  Wt[k], aD[o]);
                            aS2[o] = fmaf(vs2, Wt[k], aS2[o]);
                            aD2[o] = fmaf(vd2, Wt[k], aD2[o]);
                        }
                    }
                }
            }
        }
        int cb = qb * 4;
        #pragma unroll
        for (int o = 0; o < 4; ++o) {
            h0[r * HS + cb + o] = aS[o];
            h1[r * HS + cb + o] = aD[o];
            h2[r * HS + cb + o] = aS2[o];
            h3[r * HS + cb + o] = aD2[o];
        }
    }
    __syncthreads();

    // ---- Phase 3: vertical conv + SSIM epilogue (4 output rows/thread) ----
    float ssim_acc = 0.f;
    {
        int col = tid & 31;
        int rq  = (tid >> 5) * 4;
        float aS[4]  = {0.f, 0.f, 0.f, 0.f};
        float aD[4]  = {0.f, 0.f, 0.f, 0.f};
        float aS2[4] = {0.f, 0.f, 0.f, 0.f};
        float aD2[4] = {0.f, 0.f, 0.f, 0.f};
        #pragma unroll
        for (int j = 0; j < 19; ++j) {
            int row = rq + j;
            float vs  = h0[row * HS + col];
            float vd  = h1[row * HS + col];
            float vs2 = h2[row * HS + col];
            float vd2 = h3[row * HS + col];
            #pragma unroll
            for (int o = 0; o < 4; ++o) {
                int k = j - o;
                if (k >= 0 && k < 16) {
                    aS[o]  = fmaf(vs,  Wt[k], aS[o]);
                    aD[o]  = fmaf(vd,  Wt[k], aD[o]);
                    aS2[o] = fmaf(vs2, Wt[k], aS2[o]);
                    aD2[o] = fmaf(vd2, Wt[k], aD2[o]);
                }
            }
        }
        #pragma unroll
        for (int o = 0; o < 4; ++o) {
            int oy = y0 + rq + o;
            int ox = x0 + col;
            if (oy < OUTW && ox < OUTW) {
                float muS = aS[o], muD = aD[o];
                float muS2 = muS * muS, muD2 = muD * muD;
                float A  = 0.5f * (muS2 - muD2);          // 2*mu1*mu2
                float Bm = 0.5f * (muS2 + muD2);          // mu1^2 + mu2^2
                float Es = 0.5f * (aS2[o] - aD2[o]);      // 2*E[x1*x2]
                float Eb = 0.5f * (aS2[o] + aD2[o]);      // E[x1^2 + x2^2]
                float num = (A + C1)  * (Es - A + C2);    // (2mu12+C1)(2sig12+C2)
                float den = (Bm + C1) * (Eb - Bm + C2);   // (mu1^2+mu2^2+C1)(sig1+sig2+C2)
                ssim_acc += __fdividef(num, den);
            }
        }
    }

    // ---- block reduction -> per-plane double atomics ----
    #pragma unroll
    for (int off = 16; off; off >>= 1) {
        mse_acc  += __shfl_xor_sync(0xffffffffu, mse_acc,  off);
        ssim_acc += __shfl_xor_sync(0xffffffffu, ssim_acc, off);
    }
    if ((tid & 31) == 0) { red_m[tid >> 5] = mse_acc; red_s[tid >> 5] = ssim_acc; }
    __syncthreads();
    if (tid == 0) {
        float m = 0.f, s = 0.f;
        #pragma unroll
        for (int w = 0; w < 8; ++w) { m += red_m[w]; s += red_s[w]; }
        atomicAdd(&g_mse_parts[plane],  (double)m);
        atomicAdd(&g_ssim_parts[plane], (double)s);
    }
}

__global__ void finalize_kernel(float* out) {
    double m = 0.0, s = 0.0;
    for (int i = 0; i < PLANES; ++i) { m += g_mse_parts[i]; s += g_ssim_parts[i]; }
    double mse  = m / 25165824.0;   // 32*3*512*512
    double ssim = s / 23712864.0;   // 96*497*497
    out[0] = (float)(0.7 * mse + 0.3 * (1.0 - ssim));
}

extern "C" void kernel_launch(void* const* d_in, const int* in_sizes, int n_in,
                              void* d_out, int out_size) {
    const float* o = (const float*)d_in[0];
    const float* t = (const float*)d_in[1];
    zero_accum_kernel<<<1, 128>>>();
    dim3 grid(16, 16, PLANES);   // 16x16 tiles of 32x32 outputs, 96 planes
    ssim_mse_kernel<<<grid, 256>>>(o, t);
    finalize_kernel<<<1, 1>>>((float*)d_out);
}